// round 5
// baseline (speedup 1.0000x reference)
#include <cuda_runtime.h>
#include <cstdint>

#define NT 1024
#define NH 2048
#define NI 2048
#define NEXP 16
#define NTOP 4
#define NSLOT (NT*NTOP)
#define NBLKS 64
#define ALPHA 1.702f
#define FLIMIT 7.0f
#define NCHUNK 64            // K chunks of 32 floats

#define STRW 36              // padded words per smem row
#define STRB 144
#define AW   (128*STRW)      // 4608 words: A area per stage
#define STAGE_W (2*AW)       // 9216 words = 36864 B per stage (A+B)
#define NSTG 3
#define DSMEM_BYTES (NSTG*STAGE_W*4)   // 110592

// ---------------- scratch ----------------
__device__ int   g_tok_exp[NSLOT];
__device__ float g_tok_w[NSLOT];
__device__ int   g_counts[NEXP];
__device__ int   g_offsets[NEXP];
__device__ int   g_token_list[NSLOT];
__device__ int   g_slot_of[NSLOT];
__device__ float g_xr[(size_t)NT * NH];        // pre-rounded x (tf32-in-f32)
__device__ float g_hbuf[(size_t)NSLOT * NI];   // pre-rounded h
__device__ float g_obuf[(size_t)NSLOT * NH];

// ---------------- helpers ----------------
__device__ __forceinline__ float rna(float x){
    uint32_t r; asm("cvt.rna.tf32.f32 %0, %1;" : "=r"(r) : "f"(x));
    return __uint_as_float(r);
}
__device__ __forceinline__ uint32_t smem_u32(const void* p){
    uint32_t a;
    asm("{ .reg .u64 t; cvta.to.shared.u64 t, %1; cvt.u32.u64 %0, t; }" : "=r"(a) : "l"(p));
    return a;
}
__device__ __forceinline__ void cp16(uint32_t dst, const void* src){
    asm volatile("cp.async.cg.shared.global [%0], [%1], 16;" :: "r"(dst), "l"(src) : "memory");
}
__device__ __forceinline__ void cp_commit(){ asm volatile("cp.async.commit_group;" ::: "memory"); }
__device__ __forceinline__ void cp_wait1(){ asm volatile("cp.async.wait_group 1;" ::: "memory"); }

__device__ __forceinline__ void mma_tf32(float d[4], const uint32_t a[4], const uint32_t b[2]){
    asm volatile("mma.sync.aligned.m16n8k8.row.col.f32.tf32.tf32.f32 "
        "{%0,%1,%2,%3},{%4,%5,%6,%7},{%8,%9},{%0,%1,%2,%3};"
        : "+f"(d[0]),"+f"(d[1]),"+f"(d[2]),"+f"(d[3])
        : "r"(a[0]),"r"(a[1]),"r"(a[2]),"r"(a[3]),"r"(b[0]),"r"(b[1]));
}
__device__ __forceinline__ float act_fn(float g, float u){
    g = fminf(g, FLIMIT);
    u = fminf(fmaxf(u, -FLIMIT), FLIMIT);
    float sig = __fdividef(1.f, 1.f + __expf(-ALPHA*g));
    return (u + 1.f) * (g * sig);
}
__device__ __forceinline__ void sts_rna4(float* d, float4 v, float s){
    *(float4*)d = make_float4(rna(v.x*s), rna(v.y*s), rna(v.z*s), rna(v.w*s));
}

// ---------------- K0: pre-round x to tf32 ----------------
__global__ void prep_x_kernel(const float* __restrict__ x)
{
    const int i = blockIdx.x * blockDim.x + threadIdx.x;
    float4 v = *(const float4*)(x + (size_t)i*4);
    v.x = rna(v.x); v.y = rna(v.y); v.z = rna(v.z); v.w = rna(v.w);
    *(float4*)(g_xr + (size_t)i*4) = v;
}

// ---------------- K1: router ----------------
__global__ void router_kernel(const float* __restrict__ x,
                              const float* __restrict__ rw,
                              const float* __restrict__ rb)
{
    __shared__ float sx[NH];
    __shared__ float slog[NEXP];
    const int t = blockIdx.x;
    for (int i = threadIdx.x; i < NH; i += blockDim.x)
        sx[i] = x[(size_t)t*NH + i];
    __syncthreads();
    const int w = threadIdx.x >> 5;
    const int lane = threadIdx.x & 31;
    const float* wr = rw + (size_t)w*NH;
    float s = 0.f;
    for (int i = lane; i < NH; i += 32) s += sx[i]*wr[i];
    #pragma unroll
    for (int o=16;o>0;o>>=1) s += __shfl_xor_sync(0xffffffffu, s, o);
    if (lane==0) slog[w] = s + rb[w];
    __syncthreads();
    if (threadIdx.x==0){
        float v[NEXP];
        #pragma unroll
        for (int e=0;e<NEXP;e++) v[e]=slog[e];
        int idx[NTOP]; float val[NTOP];
        #pragma unroll
        for (int k=0;k<NTOP;k++){
            int bi=0; float bv=v[0];
            #pragma unroll
            for (int e=1;e<NEXP;e++){ if (v[e]>bv){bv=v[e];bi=e;} }
            idx[k]=bi; val[k]=bv; v[bi]=-3.4e38f;
        }
        float mx=val[0], ssum=0.f, ev[NTOP];
        #pragma unroll
        for(int k=0;k<NTOP;k++){ ev[k]=expf(val[k]-mx); ssum+=ev[k]; }
        float inv = 1.f/ssum;
        #pragma unroll
        for(int k=0;k<NTOP;k++){
            g_tok_exp[t*NTOP+k]=idx[k];
            g_tok_w[t*NTOP+k]=ev[k]*inv;
        }
    }
}

// ---------------- K2: build per-expert token lists ----------------
__global__ void build_lists_kernel()
{
    __shared__ int sc[NEXP], so[NEXP], scur[NEXP];
    const int t = threadIdx.x;
    if (t < NEXP) sc[t]=0;
    __syncthreads();
    int ex[NTOP];
    #pragma unroll
    for (int k=0;k<NTOP;k++){ ex[k]=g_tok_exp[t*NTOP+k]; atomicAdd(&sc[ex[k]],1); }
    __syncthreads();
    if (t==0){
        int acc=0;
        for(int e=0;e<NEXP;e++){ so[e]=acc; acc+=sc[e]; }
    }
    __syncthreads();
    if (t<NEXP){ g_counts[t]=sc[t]; g_offsets[t]=so[t]; scur[t]=so[t]; }
    __syncthreads();
    #pragma unroll
    for (int k=0;k<NTOP;k++){
        int slot = atomicAdd(&scur[ex[k]],1);
        g_token_list[slot]=t;
        g_slot_of[t*NTOP+k]=slot;
    }
}

// ================= GEMM core macro pieces =================
// 256 thr, 8 warps: warp m = wid&3 (32 rows), warp n = wid>>2 (64 cols).
// Stage layout: [A 128x36][B 128x36] words; 3 stages.

// ---------------- K3: gate+up GEMM + activation ----------------
// BN=128 smem-B rows: 0-63 gate (I-cols n0..n0+63), 64-127 up (same cols).
__global__ void __launch_bounds__(256,2)
gateup_kernel(const float* __restrict__ gblk, const float* __restrict__ gscl,
              const float* __restrict__ gbia,
              const float* __restrict__ ublk, const float* __restrict__ uscl,
              const float* __restrict__ ubia)
{
    extern __shared__ float sm[];
    __shared__ int sTok[128];
    __shared__ float sGb[64], sUb[64];

    const int e   = blockIdx.y >> 3;
    const int mt  = blockIdx.y & 7;
    const int M   = g_counts[e];
    if (mt*128 >= M) return;
    const int Mrows = min(128, M - mt*128);
    const int off = g_offsets[e];
    const int n0  = blockIdx.x * 64;
    const int tid = threadIdx.x;
    const int wid = tid >> 5;
    const int lane = tid & 31;

    if (tid < 128){
        int ml = mt*128 + tid; if (ml > M-1) ml = M-1;
        sTok[tid] = g_token_list[off + ml];
    }
    if (tid < 64){
        sGb[tid] = gbia[(size_t)e*NI + n0 + tid];
        sUb[tid] = ubia[(size_t)e*NI + n0 + tid];
    }
    __syncthreads();

    // A staging: 128 rows x 8 segs = 1024 -> 4 cp.async per thread
    const float* srcA[4]; uint32_t offA[4];
    const uint32_t smemBase = smem_u32(sm);
    #pragma unroll
    for (int j=0;j<4;j++){
        int id = tid + 256*j;
        int r = id>>3, s = id&7;
        srcA[j] = g_xr + (size_t)sTok[r]*NH + s*4;
        offA[j] = (uint32_t)(r*STRB + s*16);
    }
    // B staging: 4 float4 per thread. j<2 -> gate rows, j>=2 -> up rows.
    const float* pB[4]; const float* pS[4]; uint32_t offB[4];
    #pragma unroll
    for (int j=0;j<4;j++){
        int id = tid + 256*j;
        int r = id>>3, s = id&7;
        size_t grow = (size_t)e*NI + (size_t)(n0 + (r & 63));
        const float* blk = (r < 64) ? gblk : ublk;
        const float* scl = (r < 64) ? gscl : uscl;
        pB[j] = blk + grow*NH + s*4;
        pS[j] = scl + grow*NBLKS;
        offB[j] = (uint32_t)(AW + r*STRW + s*4);
    }

    const int wm = (wid & 3) * 32;
    const int wn = (wid >> 2) * 64;
    const int fr = lane >> 2;
    const int fc = lane & 3;
    const bool active = (wm < Mrows);

    float acc[2][8][4];
    #pragma unroll
    for (int a=0;a<2;a++)
        #pragma unroll
        for (int b=0;b<8;b++)
            #pragma unroll
            for (int c=0;c<4;c++) acc[a][b][c]=0.f;

    // prologue: A[0]->stg0, A[1]->stg1 (async); B[0]->stg0 (sync)
    {
        #pragma unroll
        for (int j=0;j<4;j++) cp16(smemBase + offA[j], srcA[j]);
        cp_commit();
        #pragma unroll
        for (int j=0;j<4;j++) cp16(smemBase + STAGE_W*4 + offA[j], srcA[j] + 32);
        cp_commit();
        #pragma unroll
        for (int j=0;j<4;j++){
            float4 v = *(const float4*)(pB[j]);
            sts_rna4(sm + offB[j], v, pS[j][0]);
        }
        cp_wait1();
    }
    __syncthreads();

    float4 vB[4]; float sB[4];
    for (int kc=0; kc<NCHUNK; kc++){
        const int sc  = kc % NSTG;
        if (kc+2 < NCHUNK){
            const int s2 = (kc+2) % NSTG;
            const int koff = (kc+2)*32;
            #pragma unroll
            for (int j=0;j<4;j++) cp16(smemBase + s2*(STAGE_W*4) + offA[j], srcA[j] + koff);
        }
        cp_commit();
        if (kc+1 < NCHUNK){
            const int koff = (kc+1)*32;
            #pragma unroll
            for (int j=0;j<4;j++){ vB[j] = *(const float4*)(pB[j] + koff); sB[j] = pS[j][kc+1]; }
        }
        if (active){
            const float* Ab = sm + sc*STAGE_W;
            const float* Bb = Ab + AW;
            #pragma unroll
            for (int ks=0; ks<4; ks++){
                const int kk = ks*8 + fc;
                uint32_t af[2][4];
                #pragma unroll
                for (int m2=0;m2<2;m2++){
                    const int r = wm + m2*16 + fr;
                    af[m2][0] = __float_as_uint(Ab[r*STRW + kk]);
                    af[m2][1] = __float_as_uint(Ab[(r+8)*STRW + kk]);
                    af[m2][2] = __float_as_uint(Ab[r*STRW + kk+4]);
                    af[m2][3] = __float_as_uint(Ab[(r+8)*STRW + kk+4]);
                }
                #pragma unroll
                for (int nt=0; nt<8; nt++){
                    const int c = wn + nt*8 + fr;
                    uint32_t b2[2] = {__float_as_uint(Bb[c*STRW + kk]),
                                      __float_as_uint(Bb[c*STRW + kk+4])};
                    #pragma unroll
                    for (int m2=0;m2<2;m2++) mma_tf32(acc[m2][nt], af[m2], b2);
                }
            }
        }
        if (kc+1 < NCHUNK){
            const int s1 = (kc+1) % NSTG;
            #pragma unroll
            for (int j=0;j<4;j++) sts_rna4(sm + s1*STAGE_W + offB[j], vB[j], sB[j]);
        }
        cp_wait1();
        __syncthreads();
    }

    // epilogue: gate warps (wn==0) stash raw accs; up warps combine.
    float* G = sm;   // 128*72*4 = 36864 B
    if (wn == 0 && active){
        #pragma unroll
        for (int m2=0;m2<2;m2++){
            #pragma unroll
            for (int nt=0;nt<8;nt++){
                const int rl = wm + m2*16 + fr;
                const int c  = nt*8 + fc*2;
                *(float2*)&G[rl*72 + c]     = make_float2(acc[m2][nt][0], acc[m2][nt][1]);
                *(float2*)&G[(rl+8)*72 + c] = make_float2(acc[m2][nt][2], acc[m2][nt][3]);
            }
        }
    }
    __syncthreads();
    if (wn == 64 && active){
        #pragma unroll
        for (int m2=0;m2<2;m2++){
            #pragma unroll
            for (int nt=0;nt<8;nt++){
                const int rl = wm + m2*16 + fr;
                const int cu = nt*8 + fc*2;
                const float gb0 = sGb[cu], gb1 = sGb[cu+1];
                const float ub0 = sUb[cu], ub1 = sUb[cu+1];
                if (rl < Mrows){
                    float2 gp = *(float2*)&G[rl*72 + cu];
                    float h0 = rna(act_fn(gp.x+gb0, acc[m2][nt][0]+ub0));
                    float h1 = rna(act_fn(gp.y+gb1, acc[m2][nt][1]+ub1));
                    *(float2*)&g_hbuf[(size_t)(off + mt*128 + rl)*NI + n0 + cu] = make_float2(h0,h1);
                }
                if (rl+8 < Mrows){
                    float2 gp = *(float2*)&G[(rl+8)*72 + cu];
                    float h0 = rna(act_fn(gp.x+gb0, acc[m2][nt][2]+ub0));
                    float h1 = rna(act_fn(gp.y+gb1, acc[m2][nt][3]+ub1));
                    *(float2*)&g_hbuf[(size_t)(off + mt*128 + rl+8)*NI + n0 + cu] = make_float2(h0,h1);
                }
            }
        }
    }
}

// ---------------- K4: down GEMM + bias ----------------
__global__ void __launch_bounds__(256,2)
down_kernel(const float* __restrict__ dblk, const float* __restrict__ dscl,
            const float* __restrict__ dbia)
{
    extern __shared__ float sm[];
    __shared__ int sRow[128];
    __shared__ float sDb[128];

    const int e   = blockIdx.y >> 3;
    const int mt  = blockIdx.y & 7;
    const int M   = g_counts[e];
    if (mt*128 >= M) return;
    const int Mrows = min(128, M - mt*128);
    const int off = g_offsets[e];
    const int n0  = blockIdx.x * 128;
    const int tid = threadIdx.x;
    const int wid = tid >> 5;
    const int lane = tid & 31;

    if (tid < 128){
        int ml = mt*128 + tid; if (ml > M-1) ml = M-1;
        sRow[tid] = off + ml;
        sDb[tid] = dbia[(size_t)e*NH + n0 + tid];
    }
    __syncthreads();

    const float* srcA[4]; uint32_t offA[4];
    const uint32_t smemBase = smem_u32(sm);
    #pragma unroll
    for (int j=0;j<4;j++){
        int id = tid + 256*j;
        int r = id>>3, s = id&7;
        srcA[j] = g_hbuf + (size_t)sRow[r]*NI + s*4;
        offA[j] = (uint32_t)(r*STRB + s*16);
    }
    const float* pB[4]; const float* pS[4]; uint32_t offB[4];
    #pragma unroll
    for (int j=0;j<4;j++){
        int id = tid + 256*j;
        int r = id>>3, s = id&7;
        size_t grow = (size_t)e*NH + (size_t)(n0 + r);
        pB[j] = dblk + grow*NI + s*4;
        pS[j] = dscl + grow*NBLKS;
        offB[j] = (uint32_t)(AW + r*STRW + s*4);
    }

    const int wm = (wid & 3) * 32;
    const int wn = (wid >> 2) * 64;
    const int fr = lane >> 2;
    const int fc = lane & 3;
    const bool active = (wm < Mrows);

    float acc[2][8][4];
    #pragma unroll
    for (int a=0;a<2;a++)
        #pragma unroll
        for (int b=0;b<8;b++)
            #pragma unroll
            for (int c=0;c<4;c++) acc[a][b][c]=0.f;

    {
        #pragma unroll
        for (int j=0;j<4;j++) cp16(smemBase + offA[j], srcA[j]);
        cp_commit();
        #pragma unroll
        for (int j=0;j<4;j++) cp16(smemBase + STAGE_W*4 + offA[j], srcA[j] + 32);
        cp_commit();
        #pragma unroll
        for (int j=0;j<4;j++){
            float4 v = *(const float4*)(pB[j]);
            sts_rna4(sm + offB[j], v, pS[j][0]);
        }
        cp_wait1();
    }
    __syncthreads();

    float4 vB[4]; float sB[4];
    for (int kc=0; kc<NCHUNK; kc++){
        const int sc = kc % NSTG;
        if (kc+2 < NCHUNK){
            const int s2 = (kc+2) % NSTG;
            const int koff = (kc+2)*32;
            #pragma unroll
            for (int j=0;j<4;j++) cp16(smemBase + s2*(STAGE_W*4) + offA[j], srcA[j] + koff);
        }
        cp_commit();
        if (kc+1 < NCHUNK){
            const int koff = (kc+1)*32;
            #pragma unroll
            for (int j=0;j<4;j++){ vB[j] = *(const float4*)(pB[j] + koff); sB[j] = pS[j][kc+1]; }
        }
        if (active){
            const float* Ab = sm + sc*STAGE_W;
            const float* Bb = Ab + AW;
            #pragma unroll
            for (int ks=0; ks<4; ks++){
                const int kk = ks*8 + fc;
                uint32_t af[2][4];
                #pragma unroll
                for (int m2=0;m2<2;m2++){
                    const int r = wm + m2*16 + fr;
                    af[m2][0] = __float_as_uint(Ab[r*STRW + kk]);
                    af[m2][1] = __float_as_uint(Ab[(r+8)*STRW + kk]);
                    af[m2][2] = __float_as_uint(Ab[r*STRW + kk+4]);
                    af[m2][3] = __float_as_uint(Ab[(r+8)*STRW + kk+4]);
                }
                #pragma unroll
                for (int nt=0; nt<8; nt++){
                    const int c = wn + nt*8 + fr;
                    uint32_t b2[2] = {__float_as_uint(Bb[c*STRW + kk]),
                                      __float_as_uint(Bb[c*STRW + kk+4])};
                    #pragma unroll
                    for (int m2=0;m2<2;m2++) mma_tf32(acc[m2][nt], af[m2], b2);
                }
            }
        }
        if (kc+1 < NCHUNK){
            const int s1 = (kc+1) % NSTG;
            #pragma unroll
            for (int j=0;j<4;j++) sts_rna4(sm + s1*STAGE_W + offB[j], vB[j], sB[j]);
        }
        cp_wait1();
        __syncthreads();
    }

    if (active){
        #pragma unroll
        for (int m2=0;m2<2;m2++){
            #pragma unroll
            for (int nt=0;nt<8;nt++){
                const int rl = wm + m2*16 + fr;
                const int cg = wn + nt*8 + fc*2;
                const float b0 = sDb[cg], b1 = sDb[cg+1];
                if (rl < Mrows){
                    *(float2*)&g_obuf[(size_t)(off + mt*128 + rl)*NH + n0 + cg] =
                        make_float2(acc[m2][nt][0]+b0, acc[m2][nt][1]+b1);
                }
                if (rl+8 < Mrows){
                    *(float2*)&g_obuf[(size_t)(off + mt*128 + rl+8)*NH + n0 + cg] =
                        make_float2(acc[m2][nt][2]+b0, acc[m2][nt][3]+b1);
                }
            }
        }
    }
}

// ---------------- K5: weighted combine ----------------
__global__ void combine_kernel(float* __restrict__ out)
{
    const int t = blockIdx.x;
    int sl[NTOP]; float w[NTOP];
    #pragma unroll
    for (int k=0;k<NTOP;k++){ sl[k]=g_slot_of[t*NTOP+k]; w[k]=g_tok_w[t*NTOP+k]; }
    for (int i = threadIdx.x; i < NH/4; i += blockDim.x){
        float4 a = make_float4(0.f,0.f,0.f,0.f);
        #pragma unroll
        for (int k=0;k<NTOP;k++){
            float4 v = *(const float4*)&g_obuf[(size_t)sl[k]*NH + i*4];
            a.x += w[k]*v.x; a.y += w[k]*v.y; a.z += w[k]*v.z; a.w += w[k]*v.w;
        }
        *(float4*)&out[(size_t)t*NH + i*4] = a;
    }
}

// ---------------- launch ----------------
extern "C" void kernel_launch(void* const* d_in, const int* in_sizes, int n_in,
                              void* d_out, int out_size)
{
    const float* x    = (const float*)d_in[0];
    const float* rw   = (const float*)d_in[1];
    const float* rb   = (const float*)d_in[2];
    const float* gblk = (const float*)d_in[3];
    const float* gscl = (const float*)d_in[4];
    const float* gbia = (const float*)d_in[5];
    const float* ublk = (const float*)d_in[6];
    const float* uscl = (const float*)d_in[7];
    const float* ubia = (const float*)d_in[8];
    const float* dblk = (const float*)d_in[9];
    const float* dscl = (const float*)d_in[10];
    const float* dbia = (const float*)d_in[11];
    float* out = (float*)d_out;

    cudaFuncSetAttribute(gateup_kernel, cudaFuncAttributeMaxDynamicSharedMemorySize, DSMEM_BYTES);
    cudaFuncSetAttribute(down_kernel,   cudaFuncAttributeMaxDynamicSharedMemorySize, DSMEM_BYTES);

    prep_x_kernel<<<(NT*NH/4)/256, 256>>>(x);
    router_kernel<<<NT, 512>>>(x, rw, rb);
    build_lists_kernel<<<1, NT>>>();
    gateup_kernel<<<dim3(NI/64, NEXP*8), 256, DSMEM_BYTES>>>(gblk, gscl, gbia, ublk, uscl, ubia);
    down_kernel<<<dim3(NH/128, NEXP*8), 256, DSMEM_BYTES>>>(dblk, dscl, dbia);
    combine_kernel<<<NT, 256>>>(out);
}

// round 6
// speedup vs baseline: 1.1844x; 1.1844x over previous
#include <cuda_runtime.h>
#include <cstdint>

#define NT 1024
#define NH 2048
#define NI 2048
#define NEXP 16
#define NTOP 4
#define NSLOT (NT*NTOP)
#define NBLKS 64
#define ALPHA 1.702f
#define FLIMIT 7.0f
#define NCHUNK 64            // K chunks of 32 floats

#define STRW 36              // padded words per smem row
#define STRB 144
#define AW   (128*STRW)      // 4608 words: A area per stage
#define STAGE_W (2*AW)       // 9216 words = 36864 B per stage (A+B)
#define NSTG 3
#define DSMEM_BYTES (NSTG*STAGE_W*4)   // 110592

// ---------------- scratch ----------------
__device__ int   g_tok_exp[NSLOT];
__device__ float g_tok_w[NSLOT];
__device__ int   g_counts[NEXP];
__device__ int   g_offsets[NEXP];
__device__ int   g_token_list[NSLOT];
__device__ int   g_slot_of[NSLOT];
__device__ float g_xr[(size_t)NT * NH];        // pre-rounded x (tf32-in-f32)
__device__ float g_hbuf[(size_t)NSLOT * NI];   // pre-rounded h
__device__ float g_obuf[(size_t)NSLOT * NH];

// ---------------- helpers ----------------
__device__ __forceinline__ float rna(float x){
    uint32_t r; asm("cvt.rna.tf32.f32 %0, %1;" : "=r"(r) : "f"(x));
    return __uint_as_float(r);
}
__device__ __forceinline__ uint32_t smem_u32(const void* p){
    uint32_t a;
    asm("{ .reg .u64 t; cvta.to.shared.u64 t, %1; cvt.u32.u64 %0, t; }" : "=r"(a) : "l"(p));
    return a;
}
__device__ __forceinline__ void cp16(uint32_t dst, const void* src){
    asm volatile("cp.async.cg.shared.global [%0], [%1], 16;" :: "r"(dst), "l"(src) : "memory");
}
__device__ __forceinline__ void cp_commit(){ asm volatile("cp.async.commit_group;" ::: "memory"); }
__device__ __forceinline__ void cp_wait1(){ asm volatile("cp.async.wait_group 1;" ::: "memory"); }

__device__ __forceinline__ void ldsm4(uint32_t& r0, uint32_t& r1, uint32_t& r2, uint32_t& r3, uint32_t addr){
    asm volatile("ldmatrix.sync.aligned.m8n8.x4.shared.b16 {%0,%1,%2,%3}, [%4];"
        : "=r"(r0), "=r"(r1), "=r"(r2), "=r"(r3) : "r"(addr));
}
__device__ __forceinline__ void mma_tf32(float d[4], const uint32_t a[4], const uint32_t b[2]){
    asm volatile("mma.sync.aligned.m16n8k8.row.col.f32.tf32.tf32.f32 "
        "{%0,%1,%2,%3},{%4,%5,%6,%7},{%8,%9},{%0,%1,%2,%3};"
        : "+f"(d[0]),"+f"(d[1]),"+f"(d[2]),"+f"(d[3])
        : "r"(a[0]),"r"(a[1]),"r"(a[2]),"r"(a[3]),"r"(b[0]),"r"(b[1]));
}
__device__ __forceinline__ float act_fn(float g, float u){
    g = fminf(g, FLIMIT);
    u = fminf(fmaxf(u, -FLIMIT), FLIMIT);
    float sig = __fdividef(1.f, 1.f + __expf(-ALPHA*g));
    return (u + 1.f) * (g * sig);
}
__device__ __forceinline__ void sts_rna4(float* d, float4 v, float s){
    *(float4*)d = make_float4(rna(v.x*s), rna(v.y*s), rna(v.z*s), rna(v.w*s));
}

// ---------------- K0: pre-round x to tf32 ----------------
__global__ void prep_x_kernel(const float* __restrict__ x)
{
    const int i = blockIdx.x * blockDim.x + threadIdx.x;
    float4 v = *(const float4*)(x + (size_t)i*4);
    v.x = rna(v.x); v.y = rna(v.y); v.z = rna(v.z); v.w = rna(v.w);
    *(float4*)(g_xr + (size_t)i*4) = v;
}

// ---------------- K1: router ----------------
__global__ void router_kernel(const float* __restrict__ x,
                              const float* __restrict__ rw,
                              const float* __restrict__ rb)
{
    __shared__ float sx[NH];
    __shared__ float slog[NEXP];
    const int t = blockIdx.x;
    for (int i = threadIdx.x; i < NH; i += blockDim.x)
        sx[i] = x[(size_t)t*NH + i];
    __syncthreads();
    const int w = threadIdx.x >> 5;
    const int lane = threadIdx.x & 31;
    const float* wr = rw + (size_t)w*NH;
    float s = 0.f;
    for (int i = lane; i < NH; i += 32) s += sx[i]*wr[i];
    #pragma unroll
    for (int o=16;o>0;o>>=1) s += __shfl_xor_sync(0xffffffffu, s, o);
    if (lane==0) slog[w] = s + rb[w];
    __syncthreads();
    if (threadIdx.x==0){
        float v[NEXP];
        #pragma unroll
        for (int e=0;e<NEXP;e++) v[e]=slog[e];
        int idx[NTOP]; float val[NTOP];
        #pragma unroll
        for (int k=0;k<NTOP;k++){
            int bi=0; float bv=v[0];
            #pragma unroll
            for (int e=1;e<NEXP;e++){ if (v[e]>bv){bv=v[e];bi=e;} }
            idx[k]=bi; val[k]=bv; v[bi]=-3.4e38f;
        }
        float mx=val[0], ssum=0.f, ev[NTOP];
        #pragma unroll
        for(int k=0;k<NTOP;k++){ ev[k]=expf(val[k]-mx); ssum+=ev[k]; }
        float inv = 1.f/ssum;
        #pragma unroll
        for(int k=0;k<NTOP;k++){
            g_tok_exp[t*NTOP+k]=idx[k];
            g_tok_w[t*NTOP+k]=ev[k]*inv;
        }
    }
}

// ---------------- K2: build per-expert token lists ----------------
__global__ void build_lists_kernel()
{
    __shared__ int sc[NEXP], so[NEXP], scur[NEXP];
    const int t = threadIdx.x;
    if (t < NEXP) sc[t]=0;
    __syncthreads();
    int ex[NTOP];
    #pragma unroll
    for (int k=0;k<NTOP;k++){ ex[k]=g_tok_exp[t*NTOP+k]; atomicAdd(&sc[ex[k]],1); }
    __syncthreads();
    if (t==0){
        int acc=0;
        for(int e=0;e<NEXP;e++){ so[e]=acc; acc+=sc[e]; }
    }
    __syncthreads();
    if (t<NEXP){ g_counts[t]=sc[t]; g_offsets[t]=so[t]; scur[t]=so[t]; }
    __syncthreads();
    #pragma unroll
    for (int k=0;k<NTOP;k++){
        int slot = atomicAdd(&scur[ex[k]],1);
        g_token_list[slot]=t;
        g_slot_of[t*NTOP+k]=slot;
    }
}

// ================= GEMM cores =================
// 256 thr, 8 warps: warp m = wid&3 (32 rows), warp n = wid>>2 (64 cols).
// Stage layout: [A 128x36][B 128x36] words; 3 stages.
// Fragment loads via ldmatrix.x4.
// A lane base (per m2): row = wm + m2*16 + (lane&15); +16B if lane>=16 (k-hi half)
// B lane base (per j covering nt=2j,2j+1): row = wn + j*16 + ((lane>>4)&1)*8 + (lane&7);
//   +16B if (lane>>3)&1 (k-hi half). Regs: r0=b(2j)[0], r1=b(2j)[1], r2=b(2j+1)[0], r3=b(2j+1)[1].

// ---------------- K3: gate+up GEMM + activation ----------------
__global__ void __launch_bounds__(256,2)
gateup_kernel(const float* __restrict__ gblk, const float* __restrict__ gscl,
              const float* __restrict__ gbia,
              const float* __restrict__ ublk, const float* __restrict__ uscl,
              const float* __restrict__ ubia)
{
    extern __shared__ float sm[];
    __shared__ int sTok[128];
    __shared__ float sGb[64], sUb[64];

    const int e   = blockIdx.y >> 3;
    const int mt  = blockIdx.y & 7;
    const int M   = g_counts[e];
    if (mt*128 >= M) return;
    const int Mrows = min(128, M - mt*128);
    const int off = g_offsets[e];
    const int n0  = blockIdx.x * 64;
    const int tid = threadIdx.x;
    const int wid = tid >> 5;
    const int lane = tid & 31;

    if (tid < 128){
        int ml = mt*128 + tid; if (ml > M-1) ml = M-1;
        sTok[tid] = g_token_list[off + ml];
    }
    if (tid < 64){
        sGb[tid] = gbia[(size_t)e*NI + n0 + tid];
        sUb[tid] = ubia[(size_t)e*NI + n0 + tid];
    }
    __syncthreads();

    const uint32_t smemBase = smem_u32(sm);

    // A staging: 4 cp.async per thread
    const float* srcA[4]; uint32_t offA[4];
    #pragma unroll
    for (int j=0;j<4;j++){
        int id = tid + 256*j;
        int r = id>>3, s = id&7;
        srcA[j] = g_xr + (size_t)sTok[r]*NH + s*4;
        offA[j] = (uint32_t)(r*STRB + s*16);
    }
    // B staging: 4 float4 per thread. rows<64 gate, >=64 up.
    const float* pB[4]; const float* pS[4]; uint32_t offB[4];
    #pragma unroll
    for (int j=0;j<4;j++){
        int id = tid + 256*j;
        int r = id>>3, s = id&7;
        size_t grow = (size_t)e*NI + (size_t)(n0 + (r & 63));
        const float* blk = (r < 64) ? gblk : ublk;
        const float* scl = (r < 64) ? gscl : uscl;
        pB[j] = blk + grow*NH + s*4;
        pS[j] = scl + grow*NBLKS;
        offB[j] = (uint32_t)(AW + r*STRW + s*4);
    }

    const int wm = (wid & 3) * 32;
    const int wn = (wid >> 2) * 64;
    const int fr = lane >> 2;
    const int fc = lane & 3;
    const bool active = (wm < Mrows);

    // ldmatrix per-lane base offsets (bytes)
    uint32_t lmA[2], lmB[4];
    #pragma unroll
    for (int m2=0;m2<2;m2++)
        lmA[m2] = (uint32_t)((wm + m2*16 + (lane & 15))*STRB + (lane >> 4)*16);
    #pragma unroll
    for (int j=0;j<4;j++)
        lmB[j] = (uint32_t)(AW*4 + (wn + j*16 + ((lane>>4)&1)*8 + (lane&7))*STRB + ((lane>>3)&1)*16);

    float acc[2][8][4];
    #pragma unroll
    for (int a=0;a<2;a++)
        #pragma unroll
        for (int b=0;b<8;b++)
            #pragma unroll
            for (int c=0;c<4;c++) acc[a][b][c]=0.f;

    // prologue
    {
        #pragma unroll
        for (int j=0;j<4;j++) cp16(smemBase + offA[j], srcA[j]);
        cp_commit();
        #pragma unroll
        for (int j=0;j<4;j++) cp16(smemBase + STAGE_W*4 + offA[j], srcA[j] + 32);
        cp_commit();
        #pragma unroll
        for (int j=0;j<4;j++){
            float4 v = *(const float4*)(pB[j]);
            sts_rna4(sm + offB[j], v, pS[j][0]);
        }
        cp_wait1();
    }
    __syncthreads();

    float4 vB[4]; float sB[4];
    for (int kc=0; kc<NCHUNK; kc++){
        const int sc  = kc % NSTG;
        if (kc+2 < NCHUNK){
            const int s2 = (kc+2) % NSTG;
            const int koff = (kc+2)*32;
            #pragma unroll
            for (int j=0;j<4;j++) cp16(smemBase + s2*(STAGE_W*4) + offA[j], srcA[j] + koff);
        }
        cp_commit();
        if (kc+1 < NCHUNK){
            const int koff = (kc+1)*32;
            #pragma unroll
            for (int j=0;j<4;j++){ vB[j] = *(const float4*)(pB[j] + koff); sB[j] = pS[j][kc+1]; }
        }
        if (active){
            const uint32_t stg = smemBase + sc*(STAGE_W*4);
            #pragma unroll
            for (int ks=0; ks<4; ks++){
                uint32_t af[2][4];
                #pragma unroll
                for (int m2=0;m2<2;m2++)
                    ldsm4(af[m2][0], af[m2][1], af[m2][2], af[m2][3], stg + lmA[m2] + ks*32);
                uint32_t bf[8][2];
                #pragma unroll
                for (int j=0;j<4;j++)
                    ldsm4(bf[2*j][0], bf[2*j][1], bf[2*j+1][0], bf[2*j+1][1], stg + lmB[j] + ks*32);
                #pragma unroll
                for (int nt=0; nt<8; nt++)
                    #pragma unroll
                    for (int m2=0;m2<2;m2++) mma_tf32(acc[m2][nt], af[m2], bf[nt]);
            }
        }
        if (kc+1 < NCHUNK){
            const int s1 = (kc+1) % NSTG;
            #pragma unroll
            for (int j=0;j<4;j++) sts_rna4(sm + s1*STAGE_W + offB[j], vB[j], sB[j]);
        }
        cp_wait1();
        __syncthreads();
    }

    // epilogue: gate warps (wn==0) stash raw accs; up warps combine.
    float* G = sm;   // 128*72*4 = 36864 B
    if (wn == 0 && active){
        #pragma unroll
        for (int m2=0;m2<2;m2++){
            #pragma unroll
            for (int nt=0;nt<8;nt++){
                const int rl = wm + m2*16 + fr;
                const int c  = nt*8 + fc*2;
                *(float2*)&G[rl*72 + c]     = make_float2(acc[m2][nt][0], acc[m2][nt][1]);
                *(float2*)&G[(rl+8)*72 + c] = make_float2(acc[m2][nt][2], acc[m2][nt][3]);
            }
        }
    }
    __syncthreads();
    if (wn == 64 && active){
        #pragma unroll
        for (int m2=0;m2<2;m2++){
            #pragma unroll
            for (int nt=0;nt<8;nt++){
                const int rl = wm + m2*16 + fr;
                const int cu = nt*8 + fc*2;
                const float gb0 = sGb[cu], gb1 = sGb[cu+1];
                const float ub0 = sUb[cu], ub1 = sUb[cu+1];
                if (rl < Mrows){
                    float2 gp = *(float2*)&G[rl*72 + cu];
                    float h0 = rna(act_fn(gp.x+gb0, acc[m2][nt][0]+ub0));
                    float h1 = rna(act_fn(gp.y+gb1, acc[m2][nt][1]+ub1));
                    *(float2*)&g_hbuf[(size_t)(off + mt*128 + rl)*NI + n0 + cu] = make_float2(h0,h1);
                }
                if (rl+8 < Mrows){
                    float2 gp = *(float2*)&G[(rl+8)*72 + cu];
                    float h0 = rna(act_fn(gp.x+gb0, acc[m2][nt][2]+ub0));
                    float h1 = rna(act_fn(gp.y+gb1, acc[m2][nt][3]+ub1));
                    *(float2*)&g_hbuf[(size_t)(off + mt*128 + rl+8)*NI + n0 + cu] = make_float2(h0,h1);
                }
            }
        }
    }
}

// ---------------- K4: down GEMM + bias ----------------
__global__ void __launch_bounds__(256,2)
down_kernel(const float* __restrict__ dblk, const float* __restrict__ dscl,
            const float* __restrict__ dbia)
{
    extern __shared__ float sm[];
    __shared__ int sRow[128];
    __shared__ float sDb[128];

    const int e   = blockIdx.y >> 3;
    const int mt  = blockIdx.y & 7;
    const int M   = g_counts[e];
    if (mt*128 >= M) return;
    const int Mrows = min(128, M - mt*128);
    const int off = g_offsets[e];
    const int n0  = blockIdx.x * 128;
    const int tid = threadIdx.x;
    const int wid = tid >> 5;
    const int lane = tid & 31;

    if (tid < 128){
        int ml = mt*128 + tid; if (ml > M-1) ml = M-1;
        sRow[tid] = off + ml;
        sDb[tid] = dbia[(size_t)e*NH + n0 + tid];
    }
    __syncthreads();

    const uint32_t smemBase = smem_u32(sm);

    const float* srcA[4]; uint32_t offA[4];
    #pragma unroll
    for (int j=0;j<4;j++){
        int id = tid + 256*j;
        int r = id>>3, s = id&7;
        srcA[j] = g_hbuf + (size_t)sRow[r]*NI + s*4;
        offA[j] = (uint32_t)(r*STRB + s*16);
    }
    const float* pB[4]; const float* pS[4]; uint32_t offB[4];
    #pragma unroll
    for (int j=0;j<4;j++){
        int id = tid + 256*j;
        int r = id>>3, s = id&7;
        size_t grow = (size_t)e*NH + (size_t)(n0 + r);
        pB[j] = dblk + grow*NI + s*4;
        pS[j] = dscl + grow*NBLKS;
        offB[j] = (uint32_t)(AW + r*STRW + s*4);
    }

    const int wm = (wid & 3) * 32;
    const int wn = (wid >> 2) * 64;
    const int fr = lane >> 2;
    const int fc = lane & 3;
    const bool active = (wm < Mrows);

    uint32_t lmA[2], lmB[4];
    #pragma unroll
    for (int m2=0;m2<2;m2++)
        lmA[m2] = (uint32_t)((wm + m2*16 + (lane & 15))*STRB + (lane >> 4)*16);
    #pragma unroll
    for (int j=0;j<4;j++)
        lmB[j] = (uint32_t)(AW*4 + (wn + j*16 + ((lane>>4)&1)*8 + (lane&7))*STRB + ((lane>>3)&1)*16);

    float acc[2][8][4];
    #pragma unroll
    for (int a=0;a<2;a++)
        #pragma unroll
        for (int b=0;b<8;b++)
            #pragma unroll
            for (int c=0;c<4;c++) acc[a][b][c]=0.f;

    {
        #pragma unroll
        for (int j=0;j<4;j++) cp16(smemBase + offA[j], srcA[j]);
        cp_commit();
        #pragma unroll
        for (int j=0;j<4;j++) cp16(smemBase + STAGE_W*4 + offA[j], srcA[j] + 32);
        cp_commit();
        #pragma unroll
        for (int j=0;j<4;j++){
            float4 v = *(const float4*)(pB[j]);
            sts_rna4(sm + offB[j], v, pS[j][0]);
        }
        cp_wait1();
    }
    __syncthreads();

    float4 vB[4]; float sB[4];
    for (int kc=0; kc<NCHUNK; kc++){
        const int sc = kc % NSTG;
        if (kc+2 < NCHUNK){
            const int s2 = (kc+2) % NSTG;
            const int koff = (kc+2)*32;
            #pragma unroll
            for (int j=0;j<4;j++) cp16(smemBase + s2*(STAGE_W*4) + offA[j], srcA[j] + koff);
        }
        cp_commit();
        if (kc+1 < NCHUNK){
            const int koff = (kc+1)*32;
            #pragma unroll
            for (int j=0;j<4;j++){ vB[j] = *(const float4*)(pB[j] + koff); sB[j] = pS[j][kc+1]; }
        }
        if (active){
            const uint32_t stg = smemBase + sc*(STAGE_W*4);
            #pragma unroll
            for (int ks=0; ks<4; ks++){
                uint32_t af[2][4];
                #pragma unroll
                for (int m2=0;m2<2;m2++)
                    ldsm4(af[m2][0], af[m2][1], af[m2][2], af[m2][3], stg + lmA[m2] + ks*32);
                uint32_t bf[8][2];
                #pragma unroll
                for (int j=0;j<4;j++)
                    ldsm4(bf[2*j][0], bf[2*j][1], bf[2*j+1][0], bf[2*j+1][1], stg + lmB[j] + ks*32);
                #pragma unroll
                for (int nt=0; nt<8; nt++)
                    #pragma unroll
                    for (int m2=0;m2<2;m2++) mma_tf32(acc[m2][nt], af[m2], bf[nt]);
            }
        }
        if (kc+1 < NCHUNK){
            const int s1 = (kc+1) % NSTG;
            #pragma unroll
            for (int j=0;j<4;j++) sts_rna4(sm + s1*STAGE_W + offB[j], vB[j], sB[j]);
        }
        cp_wait1();
        __syncthreads();
    }

    if (active){
        #pragma unroll
        for (int m2=0;m2<2;m2++){
            #pragma unroll
            for (int nt=0;nt<8;nt++){
                const int rl = wm + m2*16 + fr;
                const int cg = wn + nt*8 + fc*2;
                const float b0 = sDb[cg], b1 = sDb[cg+1];
                if (rl < Mrows){
                    *(float2*)&g_obuf[(size_t)(off + mt*128 + rl)*NH + n0 + cg] =
                        make_float2(acc[m2][nt][0]+b0, acc[m2][nt][1]+b1);
                }
                if (rl+8 < Mrows){
                    *(float2*)&g_obuf[(size_t)(off + mt*128 + rl+8)*NH + n0 + cg] =
                        make_float2(acc[m2][nt][2]+b0, acc[m2][nt][3]+b1);
                }
            }
        }
    }
}

// ---------------- K5: weighted combine ----------------
__global__ void combine_kernel(float* __restrict__ out)
{
    const int t = blockIdx.x;
    int sl[NTOP]; float w[NTOP];
    #pragma unroll
    for (int k=0;k<NTOP;k++){ sl[k]=g_slot_of[t*NTOP+k]; w[k]=g_tok_w[t*NTOP+k]; }
    for (int i = threadIdx.x; i < NH/4; i += blockDim.x){
        float4 a = make_float4(0.f,0.f,0.f,0.f);
        #pragma unroll
        for (int k=0;k<NTOP;k++){
            float4 v = *(const float4*)&g_obuf[(size_t)sl[k]*NH + i*4];
            a.x += w[k]*v.x; a.y += w[k]*v.y; a.z += w[k]*v.z; a.w += w[k]*v.w;
        }
        *(float4*)&out[(size_t)t*NH + i*4] = a;
    }
}

// ---------------- launch ----------------
extern "C" void kernel_launch(void* const* d_in, const int* in_sizes, int n_in,
                              void* d_out, int out_size)
{
    const float* x    = (const float*)d_in[0];
    const float* rw   = (const float*)d_in[1];
    const float* rb   = (const float*)d_in[2];
    const float* gblk = (const float*)d_in[3];
    const float* gscl = (const float*)d_in[4];
    const float* gbia = (const float*)d_in[5];
    const float* ublk = (const float*)d_in[6];
    const float* uscl = (const float*)d_in[7];
    const float* ubia = (const float*)d_in[8];
    const float* dblk = (const float*)d_in[9];
    const float* dscl = (const float*)d_in[10];
    const float* dbia = (const float*)d_in[11];
    float* out = (float*)d_out;

    cudaFuncSetAttribute(gateup_kernel, cudaFuncAttributeMaxDynamicSharedMemorySize, DSMEM_BYTES);
    cudaFuncSetAttribute(down_kernel,   cudaFuncAttributeMaxDynamicSharedMemorySize, DSMEM_BYTES);

    prep_x_kernel<<<(NT*NH/4)/256, 256>>>(x);
    router_kernel<<<NT, 512>>>(x, rw, rb);
    build_lists_kernel<<<1, NT>>>();
    gateup_kernel<<<dim3(NI/64, NEXP*8), 256, DSMEM_BYTES>>>(gblk, gscl, gbia, ublk, uscl, ubia);
    down_kernel<<<dim3(NH/128, NEXP*8), 256, DSMEM_BYTES>>>(dblk, dscl, dbia);
    combine_kernel<<<NT, 256>>>(out);
}

// round 7
// speedup vs baseline: 1.8810x; 1.5882x over previous
#include <cuda_runtime.h>
#include <cuda_fp16.h>
#include <cstdint>

#define NT 1024
#define NH 2048
#define NI 2048
#define NEXP 16
#define NTOP 4
#define NSLOT (NT*NTOP)
#define NBLKS 64
#define ALPHA 1.702f
#define FLIMIT 7.0f
#define NCH 32               // K chunks of 64 halves

#define STRB 144             // bytes per smem row (64 halves=128B + 16B pad)
#define ABYTES (128*STRB)    // 18432
#define STAGEB (2*ABYTES)    // 36864 per stage (A+B)
#define NSTG 3
#define DSMEM_BYTES (NSTG*STAGEB)  // 110592

// ---------------- scratch ----------------
__device__ int    g_tok_exp[NSLOT];
__device__ float  g_tok_w[NSLOT];
__device__ int    g_counts[NEXP];
__device__ int    g_offsets[NEXP];
__device__ int    g_token_list[NSLOT];
__device__ int    g_slot_of[NSLOT];
__device__ __half g_xh[(size_t)NT * NH];       // fp16 x
__device__ __half g_hbuf[(size_t)NSLOT * NI];  // fp16 h
__device__ float  g_obuf[(size_t)NSLOT * NH];

// ---------------- helpers ----------------
__device__ __forceinline__ uint32_t f2h2(float a, float b){  // [lo=a, hi=b]
    __half2 h = __floats2half2_rn(a, b);
    return *(uint32_t*)&h;
}
__device__ __forceinline__ uint32_t smem_u32(const void* p){
    uint32_t a;
    asm("{ .reg .u64 t; cvta.to.shared.u64 t, %1; cvt.u32.u64 %0, t; }" : "=r"(a) : "l"(p));
    return a;
}
__device__ __forceinline__ void cp16(uint32_t dst, const void* src){
    asm volatile("cp.async.cg.shared.global [%0], [%1], 16;" :: "r"(dst), "l"(src) : "memory");
}
__device__ __forceinline__ void cp_commit(){ asm volatile("cp.async.commit_group;" ::: "memory"); }
__device__ __forceinline__ void cp_wait1(){ asm volatile("cp.async.wait_group 1;" ::: "memory"); }

__device__ __forceinline__ void ldsm4(uint32_t& r0, uint32_t& r1, uint32_t& r2, uint32_t& r3, uint32_t addr){
    asm volatile("ldmatrix.sync.aligned.m8n8.x4.shared.b16 {%0,%1,%2,%3}, [%4];"
        : "=r"(r0), "=r"(r1), "=r"(r2), "=r"(r3) : "r"(addr));
}
__device__ __forceinline__ void mma_f16(float d[4], const uint32_t a[4], const uint32_t b[2]){
    asm volatile("mma.sync.aligned.m16n8k16.row.col.f32.f16.f16.f32 "
        "{%0,%1,%2,%3},{%4,%5,%6,%7},{%8,%9},{%0,%1,%2,%3};"
        : "+f"(d[0]),"+f"(d[1]),"+f"(d[2]),"+f"(d[3])
        : "r"(a[0]),"r"(a[1]),"r"(a[2]),"r"(a[3]),"r"(b[0]),"r"(b[1]));
}
__device__ __forceinline__ float act_fn(float g, float u){
    g = fminf(g, FLIMIT);
    u = fminf(fmaxf(u, -FLIMIT), FLIMIT);
    float sig = __fdividef(1.f, 1.f + __expf(-ALPHA*g));
    return (u + 1.f) * (g * sig);
}
// scale 8 floats, convert to 4 half2, STS.128
__device__ __forceinline__ void stsB(uint32_t addr, float4 lo, float4 hi, float s){
    uint32_t a = f2h2(lo.x*s, lo.y*s);
    uint32_t b = f2h2(lo.z*s, lo.w*s);
    uint32_t c = f2h2(hi.x*s, hi.y*s);
    uint32_t d = f2h2(hi.z*s, hi.w*s);
    asm volatile("st.shared.v4.b32 [%0], {%1,%2,%3,%4};" :: "r"(addr),"r"(a),"r"(b),"r"(c),"r"(d) : "memory");
}

// ---------------- K0: x -> fp16 ----------------
__global__ void prep_x_kernel(const float* __restrict__ x)
{
    const int i = blockIdx.x * blockDim.x + threadIdx.x;   // float4 index
    float4 v = *(const float4*)(x + (size_t)i*4);
    uint2 o;
    o.x = f2h2(v.x, v.y);
    o.y = f2h2(v.z, v.w);
    *(uint2*)(g_xh + (size_t)i*4) = o;
}

// ---------------- K1: router ----------------
__global__ void router_kernel(const float* __restrict__ x,
                              const float* __restrict__ rw,
                              const float* __restrict__ rb)
{
    __shared__ float sx[NH];
    __shared__ float slog[NEXP];
    const int t = blockIdx.x;
    for (int i = threadIdx.x; i < NH; i += blockDim.x)
        sx[i] = x[(size_t)t*NH + i];
    __syncthreads();
    const int w = threadIdx.x >> 5;
    const int lane = threadIdx.x & 31;
    const float* wr = rw + (size_t)w*NH;
    float s = 0.f;
    for (int i = lane; i < NH; i += 32) s += sx[i]*wr[i];
    #pragma unroll
    for (int o=16;o>0;o>>=1) s += __shfl_xor_sync(0xffffffffu, s, o);
    if (lane==0) slog[w] = s + rb[w];
    __syncthreads();
    if (threadIdx.x==0){
        float v[NEXP];
        #pragma unroll
        for (int e=0;e<NEXP;e++) v[e]=slog[e];
        int idx[NTOP]; float val[NTOP];
        #pragma unroll
        for (int k=0;k<NTOP;k++){
            int bi=0; float bv=v[0];
            #pragma unroll
            for (int e=1;e<NEXP;e++){ if (v[e]>bv){bv=v[e];bi=e;} }
            idx[k]=bi; val[k]=bv; v[bi]=-3.4e38f;
        }
        float mx=val[0], ssum=0.f, ev[NTOP];
        #pragma unroll
        for(int k=0;k<NTOP;k++){ ev[k]=expf(val[k]-mx); ssum+=ev[k]; }
        float inv = 1.f/ssum;
        #pragma unroll
        for(int k=0;k<NTOP;k++){
            g_tok_exp[t*NTOP+k]=idx[k];
            g_tok_w[t*NTOP+k]=ev[k]*inv;
        }
    }
}

// ---------------- K2: build per-expert token lists ----------------
__global__ void build_lists_kernel()
{
    __shared__ int sc[NEXP], so[NEXP], scur[NEXP];
    const int t = threadIdx.x;
    if (t < NEXP) sc[t]=0;
    __syncthreads();
    int ex[NTOP];
    #pragma unroll
    for (int k=0;k<NTOP;k++){ ex[k]=g_tok_exp[t*NTOP+k]; atomicAdd(&sc[ex[k]],1); }
    __syncthreads();
    if (t==0){
        int acc=0;
        for(int e=0;e<NEXP;e++){ so[e]=acc; acc+=sc[e]; }
    }
    __syncthreads();
    if (t<NEXP){ g_counts[t]=sc[t]; g_offsets[t]=so[t]; scur[t]=so[t]; }
    __syncthreads();
    #pragma unroll
    for (int k=0;k<NTOP;k++){
        int slot = atomicAdd(&scur[ex[k]],1);
        g_token_list[slot]=t;
        g_slot_of[t*NTOP+k]=slot;
    }
}

// ================= GEMM cores (fp16, BK=64) =================
// 256 thr, 8 warps: wm = (wid&3)*32 rows, wn = (wid>>2)*64 cols.
// Stage: [A 128 rows x 144B][B 128 rows x 144B]; 3 stages.
// A segs: 128x8 of 16B -> 4 cp.async/thread. B segs: same -> 4 LDG-groups/thread.

// ---------------- K3: gate+up GEMM + activation ----------------
__global__ void __launch_bounds__(256,2)
gateup_kernel(const float* __restrict__ gblk, const float* __restrict__ gscl,
              const float* __restrict__ gbia,
              const float* __restrict__ ublk, const float* __restrict__ uscl,
              const float* __restrict__ ubia)
{
    extern __shared__ float smf[];
    __shared__ int sTok[128];
    __shared__ float sGb[64], sUb[64];

    const int e   = blockIdx.y >> 3;
    const int mt  = blockIdx.y & 7;
    const int M   = g_counts[e];
    if (mt*128 >= M) return;
    const int Mrows = min(128, M - mt*128);
    const int off = g_offsets[e];
    const int n0  = blockIdx.x * 64;
    const int tid = threadIdx.x;
    const int wid = tid >> 5;
    const int lane = tid & 31;

    if (tid < 128){
        int ml = mt*128 + tid; if (ml > M-1) ml = M-1;
        sTok[tid] = g_token_list[off + ml];
    }
    if (tid < 64){
        sGb[tid] = gbia[(size_t)e*NI + n0 + tid];
        sUb[tid] = ubia[(size_t)e*NI + n0 + tid];
    }
    __syncthreads();

    const uint32_t smemBase = smem_u32(smf);

    // A staging: 4 cp.async per thread (seg id = tid + 256j; r=id>>3, s=id&7)
    const __half* srcA[4]; uint32_t offA[4];
    #pragma unroll
    for (int j=0;j<4;j++){
        int id = tid + 256*j;
        int r = id>>3, s = id&7;
        srcA[j] = g_xh + (size_t)sTok[r]*NH + s*8;
        offA[j] = (uint32_t)(r*STRB + s*16);
    }
    // B staging: 4 seg-groups per thread; rows<64 gate (j=0,1), >=64 up (j=2,3)
    const float* pB[4]; const float* pS[4]; uint32_t offB[4]; int sHalf[4];
    #pragma unroll
    for (int j=0;j<4;j++){
        int id = tid + 256*j;
        int r = id>>3, s = id&7;
        size_t grow = (size_t)e*NI + (size_t)(n0 + (r & 63));
        const float* blk = (r < 64) ? gblk : ublk;
        const float* scl = (r < 64) ? gscl : uscl;
        pB[j] = blk + grow*NH + s*8;
        pS[j] = scl + grow*NBLKS;
        offB[j] = (uint32_t)(ABYTES + r*STRB + s*16);
        sHalf[j] = s >> 2;
    }

    const int wm = (wid & 3) * 32;
    const int wn = (wid >> 2) * 64;
    const int fr = lane >> 2;
    const int fc = lane & 3;
    const bool active = (wm < Mrows);

    uint32_t lmA[2], lmB[4];
    #pragma unroll
    for (int m2=0;m2<2;m2++)
        lmA[m2] = (uint32_t)((wm + m2*16 + (lane & 15))*STRB + (lane >> 4)*16);
    #pragma unroll
    for (int j=0;j<4;j++)
        lmB[j] = (uint32_t)(ABYTES + (wn + j*16 + ((lane>>4)&1)*8 + (lane&7))*STRB + ((lane>>3)&1)*16);

    float acc[2][8][4];
    #pragma unroll
    for (int a=0;a<2;a++)
        #pragma unroll
        for (int b=0;b<8;b++)
            #pragma unroll
            for (int c=0;c<4;c++) acc[a][b][c]=0.f;

    // prologue: A0->stg0, A1->stg1, B0->stg0
    {
        #pragma unroll
        for (int j=0;j<4;j++) cp16(smemBase + offA[j], srcA[j]);
        cp_commit();
        #pragma unroll
        for (int j=0;j<4;j++) cp16(smemBase + STAGEB + offA[j], srcA[j] + 64);
        cp_commit();
        #pragma unroll
        for (int j=0;j<4;j++){
            float4 lo = *(const float4*)(pB[j]);
            float4 hi = *(const float4*)(pB[j] + 4);
            stsB(smemBase + offB[j], lo, hi, pS[j][sHalf[j]]);
        }
        cp_wait1();
    }
    __syncthreads();

    for (int kc=0; kc<NCH; kc++){
        const int sc = kc % NSTG;
        const uint32_t stg = smemBase + sc*STAGEB;
        const uint32_t s1b = smemBase + ((kc+1)%NSTG)*STAGEB;
        if (kc+2 < NCH){
            const int s2 = (kc+2) % NSTG;
            const int koff = (kc+2)*64;
            #pragma unroll
            for (int j=0;j<4;j++) cp16(smemBase + s2*STAGEB + offA[j], srcA[j] + koff);
        }
        cp_commit();

        float4 lo0, hi0, lo1, hi1; float sc0 = 0.f, sc1 = 0.f;
        const bool more = (kc+1 < NCH);
        if (more){
            const int koff = (kc+1)*64;
            lo0 = *(const float4*)(pB[0] + koff); hi0 = *(const float4*)(pB[0] + koff + 4);
            lo1 = *(const float4*)(pB[1] + koff); hi1 = *(const float4*)(pB[1] + koff + 4);
            sc0 = pS[0][2*(kc+1) + sHalf[0]];
            sc1 = pS[1][2*(kc+1) + sHalf[1]];
        }
        if (active){
            #pragma unroll
            for (int ks=0; ks<2; ks++){
                uint32_t af[2][4];
                #pragma unroll
                for (int m2=0;m2<2;m2++)
                    ldsm4(af[m2][0], af[m2][1], af[m2][2], af[m2][3], stg + lmA[m2] + ks*32);
                uint32_t bf[8][2];
                #pragma unroll
                for (int j=0;j<4;j++)
                    ldsm4(bf[2*j][0], bf[2*j][1], bf[2*j+1][0], bf[2*j+1][1], stg + lmB[j] + ks*32);
                #pragma unroll
                for (int nt=0; nt<8; nt++)
                    #pragma unroll
                    for (int m2=0;m2<2;m2++) mma_f16(acc[m2][nt], af[m2], bf[nt]);
            }
        }
        if (more){
            stsB(s1b + offB[0], lo0, hi0, sc0);
            stsB(s1b + offB[1], lo1, hi1, sc1);
            const int koff = (kc+1)*64;
            lo0 = *(const float4*)(pB[2] + koff); hi0 = *(const float4*)(pB[2] + koff + 4);
            lo1 = *(const float4*)(pB[3] + koff); hi1 = *(const float4*)(pB[3] + koff + 4);
            sc0 = pS[2][2*(kc+1) + sHalf[2]];
            sc1 = pS[3][2*(kc+1) + sHalf[3]];
        }
        if (active){
            #pragma unroll
            for (int ks=2; ks<4; ks++){
                uint32_t af[2][4];
                #pragma unroll
                for (int m2=0;m2<2;m2++)
                    ldsm4(af[m2][0], af[m2][1], af[m2][2], af[m2][3], stg + lmA[m2] + ks*32);
                uint32_t bf[8][2];
                #pragma unroll
                for (int j=0;j<4;j++)
                    ldsm4(bf[2*j][0], bf[2*j][1], bf[2*j+1][0], bf[2*j+1][1], stg + lmB[j] + ks*32);
                #pragma unroll
                for (int nt=0; nt<8; nt++)
                    #pragma unroll
                    for (int m2=0;m2<2;m2++) mma_f16(acc[m2][nt], af[m2], bf[nt]);
            }
        }
        if (more){
            stsB(s1b + offB[2], lo0, hi0, sc0);
            stsB(s1b + offB[3], lo1, hi1, sc1);
        }
        cp_wait1();
        __syncthreads();
    }

    // epilogue: gate warps (wn==0) stash raw accs; up warps combine, write fp16 h.
    float* G = smf;   // 128*72*4 = 36864 B
    if (wn == 0 && active){
        #pragma unroll
        for (int m2=0;m2<2;m2++){
            #pragma unroll
            for (int nt=0;nt<8;nt++){
                const int rl = wm + m2*16 + fr;
                const int c  = nt*8 + fc*2;
                *(float2*)&G[rl*72 + c]     = make_float2(acc[m2][nt][0], acc[m2][nt][1]);
                *(float2*)&G[(rl+8)*72 + c] = make_float2(acc[m2][nt][2], acc[m2][nt][3]);
            }
        }
    }
    __syncthreads();
    if (wn == 64 && active){
        #pragma unroll
        for (int m2=0;m2<2;m2++){
            #pragma unroll
            for (int nt=0;nt<8;nt++){
                const int rl = wm + m2*16 + fr;
                const int cu = nt*8 + fc*2;
                const float gb0 = sGb[cu], gb1 = sGb[cu+1];
                const float ub0 = sUb[cu], ub1 = sUb[cu+1];
                if (rl < Mrows){
                    float2 gp = *(float2*)&G[rl*72 + cu];
                    float h0 = act_fn(gp.x+gb0, acc[m2][nt][0]+ub0);
                    float h1 = act_fn(gp.y+gb1, acc[m2][nt][1]+ub1);
                    *(uint32_t*)&g_hbuf[(size_t)(off + mt*128 + rl)*NI + n0 + cu] = f2h2(h0,h1);
                }
                if (rl+8 < Mrows){
                    float2 gp = *(float2*)&G[(rl+8)*72 + cu];
                    float h0 = act_fn(gp.x+gb0, acc[m2][nt][2]+ub0);
                    float h1 = act_fn(gp.y+gb1, acc[m2][nt][3]+ub1);
                    *(uint32_t*)&g_hbuf[(size_t)(off + mt*128 + rl+8)*NI + n0 + cu] = f2h2(h0,h1);
                }
            }
        }
    }
}

// ---------------- K4: down GEMM + bias ----------------
__global__ void __launch_bounds__(256,2)
down_kernel(const float* __restrict__ dblk, const float* __restrict__ dscl,
            const float* __restrict__ dbia)
{
    extern __shared__ float smf[];
    __shared__ int sRow[128];
    __shared__ float sDb[128];

    const int e   = blockIdx.y >> 3;
    const int mt  = blockIdx.y & 7;
    const int M   = g_counts[e];
    if (mt*128 >= M) return;
    const int Mrows = min(128, M - mt*128);
    const int off = g_offsets[e];
    const int n0  = blockIdx.x * 128;
    const int tid = threadIdx.x;
    const int wid = tid >> 5;
    const int lane = tid & 31;

    if (tid < 128){
        int ml = mt*128 + tid; if (ml > M-1) ml = M-1;
        sRow[tid] = off + ml;
        sDb[tid] = dbia[(size_t)e*NH + n0 + tid];
    }
    __syncthreads();

    const uint32_t smemBase = smem_u32(smf);

    const __half* srcA[4]; uint32_t offA[4];
    #pragma unroll
    for (int j=0;j<4;j++){
        int id = tid + 256*j;
        int r = id>>3, s = id&7;
        srcA[j] = g_hbuf + (size_t)sRow[r]*NI + s*8;
        offA[j] = (uint32_t)(r*STRB + s*16);
    }
    const float* pB[4]; const float* pS[4]; uint32_t offB[4]; int sHalf[4];
    #pragma unroll
    for (int j=0;j<4;j++){
        int id = tid + 256*j;
        int r = id>>3, s = id&7;
        size_t grow = (size_t)e*NH + (size_t)(n0 + r);
        pB[j] = dblk + grow*NI + s*8;
        pS[j] = dscl + grow*NBLKS;
        offB[j] = (uint32_t)(ABYTES + r*STRB + s*16);
        sHalf[j] = s >> 2;
    }

    const int wm = (wid & 3) * 32;
    const int wn = (wid >> 2) * 64;
    const int fr = lane >> 2;
    const int fc = lane & 3;
    const bool active = (wm < Mrows);

    uint32_t lmA[2], lmB[4];
    #pragma unroll
    for (int m2=0;m2<2;m2++)
        lmA[m2] = (uint32_t)((wm + m2*16 + (lane & 15))*STRB + (lane >> 4)*16);
    #pragma unroll
    for (int j=0;j<4;j++)
        lmB[j] = (uint32_t)(ABYTES + (wn + j*16 + ((lane>>4)&1)*8 + (lane&7))*STRB + ((lane>>3)&1)*16);

    float acc[2][8][4];
    #pragma unroll
    for (int a=0;a<2;a++)
        #pragma unroll
        for (int b=0;b<8;b++)
            #pragma unroll
            for (int c=0;c<4;c++) acc[a][b][c]=0.f;

    {
        #pragma unroll
        for (int j=0;j<4;j++) cp16(smemBase + offA[j], srcA[j]);
        cp_commit();
        #pragma unroll
        for (int j=0;j<4;j++) cp16(smemBase + STAGEB + offA[j], srcA[j] + 64);
        cp_commit();
        #pragma unroll
        for (int j=0;j<4;j++){
            float4 lo = *(const float4*)(pB[j]);
            float4 hi = *(const float4*)(pB[j] + 4);
            stsB(smemBase + offB[j], lo, hi, pS[j][sHalf[j]]);
        }
        cp_wait1();
    }
    __syncthreads();

    for (int kc=0; kc<NCH; kc++){
        const int sc = kc % NSTG;
        const uint32_t stg = smemBase + sc*STAGEB;
        const uint32_t s1b = smemBase + ((kc+1)%NSTG)*STAGEB;
        if (kc+2 < NCH){
            const int s2 = (kc+2) % NSTG;
            const int koff = (kc+2)*64;
            #pragma unroll
            for (int j=0;j<4;j++) cp16(smemBase + s2*STAGEB + offA[j], srcA[j] + koff);
        }
        cp_commit();

        float4 lo0, hi0, lo1, hi1; float sc0 = 0.f, sc1 = 0.f;
        const bool more = (kc+1 < NCH);
        if (more){
            const int koff = (kc+1)*64;
            lo0 = *(const float4*)(pB[0] + koff); hi0 = *(const float4*)(pB[0] + koff + 4);
            lo1 = *(const float4*)(pB[1] + koff); hi1 = *(const float4*)(pB[1] + koff + 4);
            sc0 = pS[0][2*(kc+1) + sHalf[0]];
            sc1 = pS[1][2*(kc+1) + sHalf[1]];
        }
        if (active){
            #pragma unroll
            for (int ks=0; ks<2; ks++){
                uint32_t af[2][4];
                #pragma unroll
                for (int m2=0;m2<2;m2++)
                    ldsm4(af[m2][0], af[m2][1], af[m2][2], af[m2][3], stg + lmA[m2] + ks*32);
                uint32_t bf[8][2];
                #pragma unroll
                for (int j=0;j<4;j++)
                    ldsm4(bf[2*j][0], bf[2*j][1], bf[2*j+1][0], bf[2*j+1][1], stg + lmB[j] + ks*32);
                #pragma unroll
                for (int nt=0; nt<8; nt++)
                    #pragma unroll
                    for (int m2=0;m2<2;m2++) mma_f16(acc[m2][nt], af[m2], bf[nt]);
            }
        }
        if (more){
            stsB(s1b + offB[0], lo0, hi0, sc0);
            stsB(s1b + offB[1], lo1, hi1, sc1);
            const int koff = (kc+1)*64;
            lo0 = *(const float4*)(pB[2] + koff); hi0 = *(const float4*)(pB[2] + koff + 4);
            lo1 = *(const float4*)(pB[3] + koff); hi1 = *(const float4*)(pB[3] + koff + 4);
            sc0 = pS[2][2*(kc+1) + sHalf[2]];
            sc1 = pS[3][2*(kc+1) + sHalf[3]];
        }
        if (active){
            #pragma unroll
            for (int ks=2; ks<4; ks++){
                uint32_t af[2][4];
                #pragma unroll
                for (int m2=0;m2<2;m2++)
                    ldsm4(af[m2][0], af[m2][1], af[m2][2], af[m2][3], stg + lmA[m2] + ks*32);
                uint32_t bf[8][2];
                #pragma unroll
                for (int j=0;j<4;j++)
                    ldsm4(bf[2*j][0], bf[2*j][1], bf[2*j+1][0], bf[2*j+1][1], stg + lmB[j] + ks*32);
                #pragma unroll
                for (int nt=0; nt<8; nt++)
                    #pragma unroll
                    for (int m2=0;m2<2;m2++) mma_f16(acc[m2][nt], af[m2], bf[nt]);
            }
        }
        if (more){
            stsB(s1b + offB[2], lo0, hi0, sc0);
            stsB(s1b + offB[3], lo1, hi1, sc1);
        }
        cp_wait1();
        __syncthreads();
    }

    if (active){
        #pragma unroll
        for (int m2=0;m2<2;m2++){
            #pragma unroll
            for (int nt=0;nt<8;nt++){
                const int rl = wm + m2*16 + fr;
                const int cg = wn + nt*8 + fc*2;
                const float b0 = sDb[cg], b1 = sDb[cg+1];
                if (rl < Mrows){
                    *(float2*)&g_obuf[(size_t)(off + mt*128 + rl)*NH + n0 + cg] =
                        make_float2(acc[m2][nt][0]+b0, acc[m2][nt][1]+b1);
                }
                if (rl+8 < Mrows){
                    *(float2*)&g_obuf[(size_t)(off + mt*128 + rl+8)*NH + n0 + cg] =
                        make_float2(acc[m2][nt][2]+b0, acc[m2][nt][3]+b1);
                }
            }
        }
    }
}

// ---------------- K5: weighted combine ----------------
__global__ void combine_kernel(float* __restrict__ out)
{
    const int t = blockIdx.x;
    int sl[NTOP]; float w[NTOP];
    #pragma unroll
    for (int k=0;k<NTOP;k++){ sl[k]=g_slot_of[t*NTOP+k]; w[k]=g_tok_w[t*NTOP+k]; }
    for (int i = threadIdx.x; i < NH/4; i += blockDim.x){
        float4 a = make_float4(0.f,0.f,0.f,0.f);
        #pragma unroll
        for (int k=0;k<NTOP;k++){
            float4 v = *(const float4*)&g_obuf[(size_t)sl[k]*NH + i*4];
            a.x += w[k]*v.x; a.y += w[k]*v.y; a.z += w[k]*v.z; a.w += w[k]*v.w;
        }
        *(float4*)&out[(size_t)t*NH + i*4] = a;
    }
}

// ---------------- launch ----------------
extern "C" void kernel_launch(void* const* d_in, const int* in_sizes, int n_in,
                              void* d_out, int out_size)
{
    const float* x    = (const float*)d_in[0];
    const float* rw   = (const float*)d_in[1];
    const float* rb   = (const float*)d_in[2];
    const float* gblk = (const float*)d_in[3];
    const float* gscl = (const float*)d_in[4];
    const float* gbia = (const float*)d_in[5];
    const float* ublk = (const float*)d_in[6];
    const float* uscl = (const float*)d_in[7];
    const float* ubia = (const float*)d_in[8];
    const float* dblk = (const float*)d_in[9];
    const float* dscl = (const float*)d_in[10];
    const float* dbia = (const float*)d_in[11];
    float* out = (float*)d_out;

    cudaFuncSetAttribute(gateup_kernel, cudaFuncAttributeMaxDynamicSharedMemorySize, DSMEM_BYTES);
    cudaFuncSetAttribute(down_kernel,   cudaFuncAttributeMaxDynamicSharedMemorySize, DSMEM_BYTES);

    prep_x_kernel<<<(NT*NH/4)/256, 256>>>(x);
    router_kernel<<<NT, 512>>>(x, rw, rb);
    build_lists_kernel<<<1, NT>>>();
    gateup_kernel<<<dim3(NI/64, NEXP*8), 256, DSMEM_BYTES>>>(gblk, gscl, gbia, ublk, uscl, ubia);
    down_kernel<<<dim3(NH/128, NEXP*8), 256, DSMEM_BYTES>>>(dblk, dscl, dbia);
    combine_kernel<<<NT, 256>>>(out);
}